// round 1
// baseline (speedup 1.0000x reference)
#include <cuda_runtime.h>
#include <math.h>

#define NB   4
#define SEQ  4096
#define EDIM 1024
#define ADIM 64

// Scratch for projected Q, K, V: [B, S, A] fp32 each (4.19 MB x 3).
__device__ float g_K[NB * SEQ * ADIM];
__device__ float g_Q[NB * SEQ * ADIM];
__device__ float g_V[NB * SEQ * ADIM];

// ---------------------------------------------------------------------------
// Fused QKV projection: X[16384,1024] @ {W_K,W_Q,W_V}^T -> g_K/g_Q/g_V
// Block: 64 rows of X, all 192 output cols. 256 threads (16x16), each thread
// computes a 4x4 micro-tile per matrix (48 accumulators).
// ---------------------------------------------------------------------------
__global__ __launch_bounds__(256, 2)
void qkv_proj(const float* __restrict__ x,
              const float* __restrict__ wk,
              const float* __restrict__ wq,
              const float* __restrict__ wv)
{
    __shared__ float Xs[64][33];
    __shared__ float Ws[3][64][33];

    const int tid  = threadIdx.x;
    const int tx   = tid & 15;
    const int ty   = tid >> 4;
    const int row0 = blockIdx.x * 64;

    float acc[3][4][4];
    #pragma unroll
    for (int m = 0; m < 3; m++)
        #pragma unroll
        for (int i = 0; i < 4; i++)
            #pragma unroll
            for (int j = 0; j < 4; j++)
                acc[m][i][j] = 0.f;

    const float* wptr[3] = { wk, wq, wv };

    for (int e0 = 0; e0 < EDIM; e0 += 32) {
        // Load X chunk [64 rows x 32 e] (512 float4, 2 per thread)
        #pragma unroll
        for (int k = 0; k < 2; k++) {
            int f  = tid + k * 256;
            int r  = f >> 3;
            int c4 = f & 7;
            float4 v = *(const float4*)(x + (size_t)(row0 + r) * EDIM + e0 + c4 * 4);
            Xs[r][c4 * 4 + 0] = v.x;
            Xs[r][c4 * 4 + 1] = v.y;
            Xs[r][c4 * 4 + 2] = v.z;
            Xs[r][c4 * 4 + 3] = v.w;
        }
        // Load W chunks [64 a x 32 e] for K, Q, V
        #pragma unroll
        for (int m = 0; m < 3; m++) {
            #pragma unroll
            for (int k = 0; k < 2; k++) {
                int f  = tid + k * 256;
                int r  = f >> 3;
                int c4 = f & 7;
                float4 v = *(const float4*)(wptr[m] + (size_t)r * EDIM + e0 + c4 * 4);
                Ws[m][r][c4 * 4 + 0] = v.x;
                Ws[m][r][c4 * 4 + 1] = v.y;
                Ws[m][r][c4 * 4 + 2] = v.z;
                Ws[m][r][c4 * 4 + 3] = v.w;
            }
        }
        __syncthreads();

        #pragma unroll 8
        for (int e = 0; e < 32; e++) {
            float av[4];
            #pragma unroll
            for (int i = 0; i < 4; i++) av[i] = Xs[ty + 16 * i][e];
            #pragma unroll
            for (int m = 0; m < 3; m++) {
                #pragma unroll
                for (int j = 0; j < 4; j++) {
                    float bv = Ws[m][tx + 16 * j][e];
                    #pragma unroll
                    for (int i = 0; i < 4; i++)
                        acc[m][i][j] = fmaf(av[i], bv, acc[m][i][j]);
                }
            }
        }
        __syncthreads();
    }

    float* dsts[3] = { g_K, g_Q, g_V };
    #pragma unroll
    for (int m = 0; m < 3; m++) {
        #pragma unroll
        for (int i = 0; i < 4; i++) {
            int row = row0 + ty + 16 * i;
            #pragma unroll
            for (int j = 0; j < 4; j++)
                dsts[m][(size_t)row * ADIM + tx + 16 * j] = acc[m][i][j];
        }
    }
}

// ---------------------------------------------------------------------------
// Causal flash attention. One block per (64-row query tile, batch).
// 256 threads (16x16), 4x4 register micro-tiles for both S=QK^T and O=PV.
// Online softmax. P tile is written back into the K smem buffer.
// Heavy (high-qi) blocks are launched first via index reversal.
// ---------------------------------------------------------------------------
__global__ __launch_bounds__(256, 2)
void attn_kernel(float* __restrict__ out)
{
    extern __shared__ float sm[];
    float* Qs = sm;                 // [64][65], pre-scaled by 1/sqrt(A)
    float* Ks = sm + 64 * 65;       // [64][65], reused for P
    float* Vs = sm + 2 * 64 * 65;   // [64][65]

    const int tid = threadIdx.x;
    const int tx  = tid & 15;
    const int ty  = tid >> 4;
    const int qi  = (int)gridDim.x - 1 - (int)blockIdx.x;  // heavy blocks first
    const int b   = blockIdx.y;
    const int q0  = qi * 64;

    const float* Qg = g_Q + ((size_t)b * SEQ + q0) * ADIM;
    const float* Kb = g_K + (size_t)b * SEQ * ADIM;
    const float* Vb = g_V + (size_t)b * SEQ * ADIM;

    // Load Q tile (64x64), pre-scale by 1/8 = 1/sqrt(64)
    #pragma unroll
    for (int k = 0; k < 4; k++) {
        int f  = tid + k * 256;
        int r  = f >> 4;
        int c4 = f & 15;
        float4 v = *(const float4*)(Qg + (size_t)r * ADIM + c4 * 4);
        Qs[r * 65 + c4 * 4 + 0] = v.x * 0.125f;
        Qs[r * 65 + c4 * 4 + 1] = v.y * 0.125f;
        Qs[r * 65 + c4 * 4 + 2] = v.z * 0.125f;
        Qs[r * 65 + c4 * 4 + 3] = v.w * 0.125f;
    }

    float m_i[4], l_i[4], o[4][4];
    #pragma unroll
    for (int i = 0; i < 4; i++) {
        m_i[i] = -1e30f;
        l_i[i] = 0.f;
        #pragma unroll
        for (int j = 0; j < 4; j++) o[i][j] = 0.f;
    }

    for (int kb = 0; kb <= qi; kb++) {
        __syncthreads();  // prev PV done with Ks/Vs; Q visible on first iter
        const float* Kg = Kb + (size_t)kb * 64 * ADIM;
        const float* Vg = Vb + (size_t)kb * 64 * ADIM;
        #pragma unroll
        for (int k = 0; k < 4; k++) {
            int f  = tid + k * 256;
            int r  = f >> 4;
            int c4 = f & 15;
            float4 kv = *(const float4*)(Kg + (size_t)r * ADIM + c4 * 4);
            Ks[r * 65 + c4 * 4 + 0] = kv.x;
            Ks[r * 65 + c4 * 4 + 1] = kv.y;
            Ks[r * 65 + c4 * 4 + 2] = kv.z;
            Ks[r * 65 + c4 * 4 + 3] = kv.w;
            float4 vv = *(const float4*)(Vg + (size_t)r * ADIM + c4 * 4);
            Vs[r * 65 + c4 * 4 + 0] = vv.x;
            Vs[r * 65 + c4 * 4 + 1] = vv.y;
            Vs[r * 65 + c4 * 4 + 2] = vv.z;
            Vs[r * 65 + c4 * 4 + 3] = vv.w;
        }
        __syncthreads();

        // S = Q K^T  (64x64 tile, 4x4 per thread)
        float s[4][4];
        #pragma unroll
        for (int i = 0; i < 4; i++)
            #pragma unroll
            for (int j = 0; j < 4; j++) s[i][j] = 0.f;

        #pragma unroll 16
        for (int e = 0; e < 64; e++) {
            float qv[4], kv[4];
            #pragma unroll
            for (int i = 0; i < 4; i++) qv[i] = Qs[(ty + 16 * i) * 65 + e];
            #pragma unroll
            for (int j = 0; j < 4; j++) kv[j] = Ks[(tx + 16 * j) * 65 + e];
            #pragma unroll
            for (int i = 0; i < 4; i++)
                #pragma unroll
                for (int j = 0; j < 4; j++)
                    s[i][j] = fmaf(qv[i], kv[j], s[i][j]);
        }

        // Causal mask on the diagonal tile (q0 == k0, local indices suffice)
        if (kb == qi) {
            #pragma unroll
            for (int i = 0; i < 4; i++)
                #pragma unroll
                for (int j = 0; j < 4; j++)
                    if (tx + 16 * j > ty + 16 * i) s[i][j] = -1e30f;
        }

        // Online softmax (row stats reduced across the 16 tx-lanes of the row)
        #pragma unroll
        for (int i = 0; i < 4; i++) {
            float ml = fmaxf(fmaxf(s[i][0], s[i][1]), fmaxf(s[i][2], s[i][3]));
            #pragma unroll
            for (int o2 = 1; o2 < 16; o2 <<= 1)
                ml = fmaxf(ml, __shfl_xor_sync(0xffffffffu, ml, o2));
            float mn = fmaxf(m_i[i], ml);
            float sc = __expf(m_i[i] - mn);
            m_i[i] = mn;
            float ls = 0.f;
            #pragma unroll
            for (int j = 0; j < 4; j++) {
                s[i][j] = __expf(s[i][j] - mn);
                ls += s[i][j];
            }
            #pragma unroll
            for (int o2 = 1; o2 < 16; o2 <<= 1)
                ls += __shfl_xor_sync(0xffffffffu, ls, o2);
            l_i[i] = l_i[i] * sc + ls;
            #pragma unroll
            for (int j = 0; j < 4; j++) o[i][j] *= sc;
        }

        __syncthreads();  // everyone done reading Ks as K
        #pragma unroll
        for (int i = 0; i < 4; i++)
            #pragma unroll
            for (int j = 0; j < 4; j++)
                Ks[(ty + 16 * i) * 65 + tx + 16 * j] = s[i][j];  // P tile
        __syncthreads();

        // O += P @ V
        #pragma unroll 16
        for (int kk = 0; kk < 64; kk++) {
            float pv[4], vv[4];
            #pragma unroll
            for (int i = 0; i < 4; i++) pv[i] = Ks[(ty + 16 * i) * 65 + kk];
            #pragma unroll
            for (int j = 0; j < 4; j++) vv[j] = Vs[kk * 65 + tx + 16 * j];
            #pragma unroll
            for (int i = 0; i < 4; i++)
                #pragma unroll
                for (int j = 0; j < 4; j++)
                    o[i][j] = fmaf(pv[i], vv[j], o[i][j]);
        }
    }

    // Epilogue: normalize and round to 4 decimals (match reference)
    float* Ob = out + ((size_t)b * SEQ + q0) * ADIM;
    #pragma unroll
    for (int i = 0; i < 4; i++) {
        float inv = 1.f / l_i[i];
        #pragma unroll
        for (int j = 0; j < 4; j++) {
            float v = o[i][j] * inv;
            Ob[(size_t)(ty + 16 * i) * ADIM + tx + 16 * j] = rintf(v * 1e4f) * 1e-4f;
        }
    }
}

extern "C" void kernel_launch(void* const* d_in, const int* in_sizes, int n_in,
                              void* d_out, int out_size)
{
    const float* x  = (const float*)d_in[0];  // embedded [4,4096,1024]
    const float* wk = (const float*)d_in[1];  // W_K [64,1024]
    const float* wq = (const float*)d_in[2];  // W_Q [64,1024]
    const float* wv = (const float*)d_in[3];  // W_V [64,1024]
    float* out = (float*)d_out;               // [4,4096,64]

    qkv_proj<<<(NB * SEQ) / 64, 256>>>(x, wk, wq, wv);

    int smem = 3 * 64 * 65 * (int)sizeof(float);  // 49920 B > 48KB default
    cudaFuncSetAttribute(attn_kernel, cudaFuncAttributeMaxDynamicSharedMemorySize, smem);
    attn_kernel<<<dim3(SEQ / 64, NB), 256, smem>>>(out);
}

// round 2
// speedup vs baseline: 2.2955x; 2.2955x over previous
#include <cuda_runtime.h>
#include <cuda_fp16.h>
#include <math.h>

#define NB   4
#define SEQ  4096
#define EDIM 1024
#define ADIM 64

// Projected Q,K,V stored as split fp16 planes (hi + lo), [B*S, A] each.
__device__ __half g_Qh[NB * SEQ * ADIM];
__device__ __half g_Ql[NB * SEQ * ADIM];
__device__ __half g_Kh[NB * SEQ * ADIM];
__device__ __half g_Kl[NB * SEQ * ADIM];
__device__ __half g_Vh[NB * SEQ * ADIM];
__device__ __half g_Vl[NB * SEQ * ADIM];

// m16n8k16 f16 MMA, f32 accumulate, in-place C.
__device__ __forceinline__ void mma16816(float d[4], const unsigned a[4], const unsigned b[2])
{
    asm volatile(
        "mma.sync.aligned.m16n8k16.row.col.f32.f16.f16.f32 "
        "{%0,%1,%2,%3}, {%4,%5,%6,%7}, {%8,%9}, {%0,%1,%2,%3};\n"
        : "+f"(d[0]), "+f"(d[1]), "+f"(d[2]), "+f"(d[3])
        : "r"(a[0]), "r"(a[1]), "r"(a[2]), "r"(a[3]), "r"(b[0]), "r"(b[1]));
}

__device__ __forceinline__ void split1(float v, __half& h, __half& l)
{
    h = __float2half_rn(v);
    l = __float2half_rn(v - __half2float(h));
}

struct alignas(16) H8 { __half h[8]; };

// ---------------------------------------------------------------------------
// QKV projection on tensor cores (fp16x2 split).
// Block: 64 rows of X, all 192 outputs. 8 warps: 4 row-groups x 2 col-groups.
// Each warp: m16 x n96 (12 n-tiles), K loop over E in chunks of 32 (2 x k16).
// ---------------------------------------------------------------------------
__global__ __launch_bounds__(256, 2)
void qkv_proj(const float* __restrict__ x,
              const float* __restrict__ wk,
              const float* __restrict__ wq,
              const float* __restrict__ wv)
{
    // row stride 40 halves (20 words) -> conflict-free fragment loads
    __shared__ __align__(16) __half Xh[64 * 40];
    __shared__ __align__(16) __half Xl[64 * 40];
    __shared__ __align__(16) __half Wh[192 * 40];
    __shared__ __align__(16) __half Wl[192 * 40];

    const int tid  = threadIdx.x;
    const int warp = tid >> 5;
    const int lane = tid & 31;
    const int g    = lane >> 2;
    const int cq   = lane & 3;
    const int rg   = warp >> 1;   // row group 0..3
    const int cg   = warp & 1;    // col group 0..1
    const int rows0 = blockIdx.x * 64;

    float acc[12][4];
    #pragma unroll
    for (int j = 0; j < 12; j++)
        #pragma unroll
        for (int i = 0; i < 4; i++) acc[j][i] = 0.f;

    for (int e0 = 0; e0 < EDIM; e0 += 32) {
        // Load + split X chunk [64 x 32]
        #pragma unroll
        for (int k = 0; k < 2; k++) {
            int f  = tid + k * 256;
            int r  = f >> 3;
            int c4 = f & 7;
            float4 v = *(const float4*)(x + (size_t)(rows0 + r) * EDIM + e0 + c4 * 4);
            float vv[4] = { v.x, v.y, v.z, v.w };
            #pragma unroll
            for (int i = 0; i < 4; i++) {
                __half h, l; split1(vv[i], h, l);
                Xh[r * 40 + c4 * 4 + i] = h;
                Xl[r * 40 + c4 * 4 + i] = l;
            }
        }
        // Load + split W chunk [192 x 32]; rows 0-63 K, 64-127 Q, 128-191 V
        #pragma unroll
        for (int k = 0; k < 6; k++) {
            int f  = tid + k * 256;
            int r  = f >> 3;
            int c4 = f & 7;
            const float* src = (r < 64)  ? wk + (size_t)r * EDIM
                             : (r < 128) ? wq + (size_t)(r - 64) * EDIM
                                         : wv + (size_t)(r - 128) * EDIM;
            float4 v = *(const float4*)(src + e0 + c4 * 4);
            float vv[4] = { v.x, v.y, v.z, v.w };
            #pragma unroll
            for (int i = 0; i < 4; i++) {
                __half h, l; split1(vv[i], h, l);
                Wh[r * 40 + c4 * 4 + i] = h;
                Wl[r * 40 + c4 * 4 + i] = l;
            }
        }
        __syncthreads();

        const unsigned* Xh32 = (const unsigned*)Xh;
        const unsigned* Xl32 = (const unsigned*)Xl;
        const unsigned* Wh32 = (const unsigned*)Wh;
        const unsigned* Wl32 = (const unsigned*)Wl;

        #pragma unroll
        for (int kc = 0; kc < 2; kc++) {
            int ab = (16 * rg + g) * 20 + 8 * kc + cq;
            unsigned ah[4] = { Xh32[ab], Xh32[ab + 160], Xh32[ab + 4], Xh32[ab + 164] };
            unsigned al[4] = { Xl32[ab], Xl32[ab + 160], Xl32[ab + 4], Xl32[ab + 164] };
            #pragma unroll
            for (int j = 0; j < 12; j++) {
                int n0 = cg * 96 + 8 * j;
                int bb = (n0 + g) * 20 + 8 * kc + cq;
                unsigned bh[2] = { Wh32[bb], Wh32[bb + 4] };
                unsigned bl[2] = { Wl32[bb], Wl32[bb + 4] };
                mma16816(acc[j], ah, bh);
                mma16816(acc[j], ah, bl);
                mma16816(acc[j], al, bh);
            }
        }
        __syncthreads();
    }

    // Epilogue: split to hi/lo planes; Q gets the 1/sqrt(64) scale.
    const int row_lo = rows0 + 16 * rg + g;
    const int row_hi = row_lo + 8;
    #pragma unroll
    for (int j = 0; j < 12; j++) {
        int colg = cg * 96 + 8 * j + 2 * cq;
        __half *dh, *dl;
        float sc = 1.f;
        int cl;
        if (colg < 64)       { dh = g_Kh; dl = g_Kl; cl = colg; }
        else if (colg < 128) { dh = g_Qh; dl = g_Ql; cl = colg - 64; sc = 0.125f; }
        else                 { dh = g_Vh; dl = g_Vl; cl = colg - 128; }

        float v0 = acc[j][0] * sc, v1 = acc[j][1] * sc;
        float v2 = acc[j][2] * sc, v3 = acc[j][3] * sc;
        __half h0, l0, h1, l1; split1(v0, h0, l0); split1(v1, h1, l1);
        *(__half2*)(dh + (size_t)row_lo * ADIM + cl) = __halves2half2(h0, h1);
        *(__half2*)(dl + (size_t)row_lo * ADIM + cl) = __halves2half2(l0, l1);
        split1(v2, h0, l0); split1(v3, h1, l1);
        *(__half2*)(dh + (size_t)row_hi * ADIM + cl) = __halves2half2(h0, h1);
        *(__half2*)(dl + (size_t)row_hi * ADIM + cl) = __halves2half2(l0, l1);
    }
}

// ---------------------------------------------------------------------------
// Causal flash attention on tensor cores. Block = (64 q-rows, batch);
// 4 warps, each owns 16 q-rows. Online softmax on mma C-fragments.
// ---------------------------------------------------------------------------
#define ST 72   // smem row stride in halves
#define SW 36   // smem row stride in 32-bit words
#define OFF_KH 0
#define OFF_KL 4608
#define OFF_VH 9216
#define OFF_VL 13824
#define OFF_PH 18432
#define OFF_PL 23040
#define SMEM_HALVES 27648

__global__ __launch_bounds__(128, 4)
void attn_kernel(float* __restrict__ out)
{
    extern __shared__ __align__(16) __half sh[];

    const int tid  = threadIdx.x;
    const int w    = tid >> 5;
    const int lane = tid & 31;
    const int g    = lane >> 2;
    const int cq   = lane & 3;
    const int qi   = (int)gridDim.x - 1 - (int)blockIdx.x;  // heavy blocks first
    const int b    = blockIdx.y;
    const int q0   = qi * 64;

    // Resident Q fragments (pre-scaled at projection)
    unsigned qh[4][4], ql[4][4];
    {
        size_t rl = (size_t)(b * SEQ + q0 + 16 * w + g) * ADIM;
        size_t rh = rl + 8 * ADIM;
        #pragma unroll
        for (int kc = 0; kc < 4; kc++) {
            int off = 16 * kc + 2 * cq;
            qh[kc][0] = *(const unsigned*)(g_Qh + rl + off);
            qh[kc][1] = *(const unsigned*)(g_Qh + rh + off);
            qh[kc][2] = *(const unsigned*)(g_Qh + rl + off + 8);
            qh[kc][3] = *(const unsigned*)(g_Qh + rh + off + 8);
            ql[kc][0] = *(const unsigned*)(g_Ql + rl + off);
            ql[kc][1] = *(const unsigned*)(g_Ql + rh + off);
            ql[kc][2] = *(const unsigned*)(g_Ql + rl + off + 8);
            ql[kc][3] = *(const unsigned*)(g_Ql + rh + off + 8);
        }
    }

    float o[8][4];
    #pragma unroll
    for (int j = 0; j < 8; j++)
        #pragma unroll
        for (int i = 0; i < 4; i++) o[j][i] = 0.f;
    float m_lo = -1e30f, m_hi = -1e30f, l_lo = 0.f, l_hi = 0.f;

    for (int kb = 0; kb <= qi; kb++) {
        __syncthreads();
        // ---- load K tile (hi/lo planes), rows [key][adim]
        {
            const __half* sKh = g_Kh + (size_t)(b * SEQ + kb * 64) * ADIM;
            const __half* sKl = g_Kl + (size_t)(b * SEQ + kb * 64) * ADIM;
            #pragma unroll
            for (int k = 0; k < 4; k++) {
                int f = tid + 128 * k;
                int r = f >> 3, c = f & 7;
                *(uint4*)(sh + OFF_KH + r * ST + 8 * c) = *(const uint4*)(sKh + r * ADIM + 8 * c);
                *(uint4*)(sh + OFF_KL + r * ST + 8 * c) = *(const uint4*)(sKl + r * ADIM + 8 * c);
            }
        }
        // ---- load V transposed: Vt[adim][key]
        {
            int kp = tid & 31;
            int a0 = (tid >> 5) * 16;
            const __half* r0h = g_Vh + (size_t)(b * SEQ + kb * 64 + 2 * kp) * ADIM + a0;
            const __half* r0l = g_Vl + (size_t)(b * SEQ + kb * 64 + 2 * kp) * ADIM + a0;
            H8 xh0 = *(const H8*)(r0h),      xh1 = *(const H8*)(r0h + 8);
            H8 yh0 = *(const H8*)(r0h + 64), yh1 = *(const H8*)(r0h + 72);
            H8 xl0 = *(const H8*)(r0l),      xl1 = *(const H8*)(r0l + 8);
            H8 yl0 = *(const H8*)(r0l + 64), yl1 = *(const H8*)(r0l + 72);
            #pragma unroll
            for (int i = 0; i < 8; i++) {
                *(__half2*)(sh + OFF_VH + (a0 + i) * ST + 2 * kp)     = __halves2half2(xh0.h[i], yh0.h[i]);
                *(__half2*)(sh + OFF_VH + (a0 + 8 + i) * ST + 2 * kp) = __halves2half2(xh1.h[i], yh1.h[i]);
                *(__half2*)(sh + OFF_VL + (a0 + i) * ST + 2 * kp)     = __halves2half2(xl0.h[i], yl0.h[i]);
                *(__half2*)(sh + OFF_VL + (a0 + 8 + i) * ST + 2 * kp) = __halves2half2(xl1.h[i], yl1.h[i]);
            }
        }
        __syncthreads();

        // ---- S = Q K^T
        float s[8][4];
        #pragma unroll
        for (int j = 0; j < 8; j++)
            #pragma unroll
            for (int i = 0; i < 4; i++) s[j][i] = 0.f;

        const unsigned* Kh32 = (const unsigned*)(sh + OFF_KH);
        const unsigned* Kl32 = (const unsigned*)(sh + OFF_KL);
        #pragma unroll
        for (int kc = 0; kc < 4; kc++) {
            #pragma unroll
            for (int j = 0; j < 8; j++) {
                int bb = (8 * j + g) * SW + 8 * kc + cq;
                unsigned bh[2] = { Kh32[bb], Kh32[bb + 4] };
                unsigned bl[2] = { Kl32[bb], Kl32[bb + 4] };
                mma16816(s[j], qh[kc], bh);
                mma16816(s[j], qh[kc], bl);
                mma16816(s[j], ql[kc], bh);
            }
        }

        // ---- causal mask on diagonal tile
        if (kb == qi) {
            int r_lo = 16 * w + g, r_hi = r_lo + 8;
            #pragma unroll
            for (int j = 0; j < 8; j++) {
                int c0 = 8 * j + 2 * cq;
                if (c0     > r_lo) s[j][0] = -1e30f;
                if (c0 + 1 > r_lo) s[j][1] = -1e30f;
                if (c0     > r_hi) s[j][2] = -1e30f;
                if (c0 + 1 > r_hi) s[j][3] = -1e30f;
            }
        }

        // ---- online softmax
        float mx0 = -1e30f, mx1 = -1e30f;
        #pragma unroll
        for (int j = 0; j < 8; j++) {
            mx0 = fmaxf(mx0, fmaxf(s[j][0], s[j][1]));
            mx1 = fmaxf(mx1, fmaxf(s[j][2], s[j][3]));
        }
        mx0 = fmaxf(mx0, __shfl_xor_sync(0xffffffffu, mx0, 1));
        mx0 = fmaxf(mx0, __shfl_xor_sync(0xffffffffu, mx0, 2));
        mx1 = fmaxf(mx1, __shfl_xor_sync(0xffffffffu, mx1, 1));
        mx1 = fmaxf(mx1, __shfl_xor_sync(0xffffffffu, mx1, 2));
        float mn0 = fmaxf(m_lo, mx0), mn1 = fmaxf(m_hi, mx1);
        float sc0 = __expf(m_lo - mn0), sc1 = __expf(m_hi - mn1);
        m_lo = mn0; m_hi = mn1;
        float su0 = 0.f, su1 = 0.f;
        #pragma unroll
        for (int j = 0; j < 8; j++) {
            s[j][0] = __expf(s[j][0] - mn0);
            s[j][1] = __expf(s[j][1] - mn0);
            s[j][2] = __expf(s[j][2] - mn1);
            s[j][3] = __expf(s[j][3] - mn1);
            su0 += s[j][0] + s[j][1];
            su1 += s[j][2] + s[j][3];
        }
        su0 += __shfl_xor_sync(0xffffffffu, su0, 1);
        su0 += __shfl_xor_sync(0xffffffffu, su0, 2);
        su1 += __shfl_xor_sync(0xffffffffu, su1, 1);
        su1 += __shfl_xor_sync(0xffffffffu, su1, 2);
        l_lo = l_lo * sc0 + su0;
        l_hi = l_hi * sc1 + su1;
        #pragma unroll
        for (int j = 0; j < 8; j++) {
            o[j][0] *= sc0; o[j][1] *= sc0;
            o[j][2] *= sc1; o[j][3] *= sc1;
        }

        // ---- write P (split) into per-warp region
        #pragma unroll
        for (int j = 0; j < 8; j++) {
            int hc = 8 * j + 2 * cq;
            __half h0, l0, h1, l1;
            split1(s[j][0], h0, l0); split1(s[j][1], h1, l1);
            *(__half2*)(sh + OFF_PH + (16 * w + g) * ST + hc) = __halves2half2(h0, h1);
            *(__half2*)(sh + OFF_PL + (16 * w + g) * ST + hc) = __halves2half2(l0, l1);
            split1(s[j][2], h0, l0); split1(s[j][3], h1, l1);
            *(__half2*)(sh + OFF_PH + (16 * w + g + 8) * ST + hc) = __halves2half2(h0, h1);
            *(__half2*)(sh + OFF_PL + (16 * w + g + 8) * ST + hc) = __halves2half2(l0, l1);
        }
        __syncwarp();

        // ---- O += P V
        const unsigned* Ph32 = (const unsigned*)(sh + OFF_PH);
        const unsigned* Pl32 = (const unsigned*)(sh + OFF_PL);
        const unsigned* Vh32 = (const unsigned*)(sh + OFF_VH);
        const unsigned* Vl32 = (const unsigned*)(sh + OFF_VL);
        #pragma unroll
        for (int kc = 0; kc < 4; kc++) {
            int ab = (16 * w + g) * SW + 8 * kc + cq;
            unsigned ah[4] = { Ph32[ab], Ph32[ab + 8 * SW], Ph32[ab + 4], Ph32[ab + 8 * SW + 4] };
            unsigned al[4] = { Pl32[ab], Pl32[ab + 8 * SW], Pl32[ab + 4], Pl32[ab + 8 * SW + 4] };
            #pragma unroll
            for (int j = 0; j < 8; j++) {
                int bb = (8 * j + g) * SW + 8 * kc + cq;
                unsigned bh[2] = { Vh32[bb], Vh32[bb + 4] };
                unsigned bl[2] = { Vl32[bb], Vl32[bb + 4] };
                mma16816(o[j], ah, bh);
                mma16816(o[j], ah, bl);
                mma16816(o[j], al, bh);
            }
        }
    }

    // ---- epilogue: normalize, round to 4 decimals, store
    float inv0 = 1.f / l_lo, inv1 = 1.f / l_hi;
    int row_lo = q0 + 16 * w + g;
    int row_hi = row_lo + 8;
    #pragma unroll
    for (int j = 0; j < 8; j++) {
        int col = 8 * j + 2 * cq;
        float2 v;
        v.x = rintf(o[j][0] * inv0 * 1e4f) * 1e-4f;
        v.y = rintf(o[j][1] * inv0 * 1e4f) * 1e-4f;
        *(float2*)(out + ((size_t)(b * SEQ + row_lo) * ADIM + col)) = v;
        v.x = rintf(o[j][2] * inv1 * 1e4f) * 1e-4f;
        v.y = rintf(o[j][3] * inv1 * 1e4f) * 1e-4f;
        *(float2*)(out + ((size_t)(b * SEQ + row_hi) * ADIM + col)) = v;
    }
}

extern "C" void kernel_launch(void* const* d_in, const int* in_sizes, int n_in,
                              void* d_out, int out_size)
{
    const float* x  = (const float*)d_in[0];
    const float* wk = (const float*)d_in[1];
    const float* wq = (const float*)d_in[2];
    const float* wv = (const float*)d_in[3];
    float* out = (float*)d_out;

    qkv_proj<<<(NB * SEQ) / 64, 256>>>(x, wk, wq, wv);

    int smem = SMEM_HALVES * (int)sizeof(__half);  // 55296 B
    cudaFuncSetAttribute(attn_kernel, cudaFuncAttributeMaxDynamicSharedMemorySize, smem);
    attn_kernel<<<dim3(SEQ / 64, NB), 128, smem>>>(out);
}

// round 3
// speedup vs baseline: 3.0876x; 1.3451x over previous
#include <cuda_runtime.h>
#include <cuda_fp16.h>
#include <math.h>

#define NB   4
#define SEQ  4096
#define EDIM 1024
#define ADIM 64
#define NS   4      // KV splits per q-tile

// Projected Q,K,V stored as split fp16 planes (hi + lo), [B*S, A] each.
__device__ __half g_Qh[NB * SEQ * ADIM];
__device__ __half g_Ql[NB * SEQ * ADIM];
__device__ __half g_Kh[NB * SEQ * ADIM];
__device__ __half g_Kl[NB * SEQ * ADIM];
__device__ __half g_Vh[NB * SEQ * ADIM];
__device__ __half g_Vl[NB * SEQ * ADIM];

// Split-KV partial results: O (unnormalized), row max m, row sum l.
__device__ float g_Om[NB * NS * SEQ * ADIM];   // 16.8 MB
__device__ float g_m [NB * NS * SEQ];
__device__ float g_l [NB * NS * SEQ];

// m16n8k16 f16 MMA, f32 accumulate, in-place C.
__device__ __forceinline__ void mma16816(float d[4], const unsigned a[4], const unsigned b[2])
{
    asm volatile(
        "mma.sync.aligned.m16n8k16.row.col.f32.f16.f16.f32 "
        "{%0,%1,%2,%3}, {%4,%5,%6,%7}, {%8,%9}, {%0,%1,%2,%3};\n"
        : "+f"(d[0]), "+f"(d[1]), "+f"(d[2]), "+f"(d[3])
        : "r"(a[0]), "r"(a[1]), "r"(a[2]), "r"(a[3]), "r"(b[0]), "r"(b[1]));
}

__device__ __forceinline__ void split1(float v, __half& h, __half& l)
{
    h = __float2half_rn(v);
    l = __float2half_rn(v - __half2float(h));
}

struct alignas(16) H8 { __half h[8]; };

// ---------------------------------------------------------------------------
// QKV projection on tensor cores (fp16x2 split). Unchanged from R1.
// ---------------------------------------------------------------------------
__global__ __launch_bounds__(256, 2)
void qkv_proj(const float* __restrict__ x,
              const float* __restrict__ wk,
              const float* __restrict__ wq,
              const float* __restrict__ wv)
{
    __shared__ __align__(16) __half Xh[64 * 40];
    __shared__ __align__(16) __half Xl[64 * 40];
    __shared__ __align__(16) __half Wh[192 * 40];
    __shared__ __align__(16) __half Wl[192 * 40];

    const int tid  = threadIdx.x;
    const int warp = tid >> 5;
    const int lane = tid & 31;
    const int g    = lane >> 2;
    const int cq   = lane & 3;
    const int rg   = warp >> 1;
    const int cg   = warp & 1;
    const int rows0 = blockIdx.x * 64;

    float acc[12][4];
    #pragma unroll
    for (int j = 0; j < 12; j++)
        #pragma unroll
        for (int i = 0; i < 4; i++) acc[j][i] = 0.f;

    for (int e0 = 0; e0 < EDIM; e0 += 32) {
        #pragma unroll
        for (int k = 0; k < 2; k++) {
            int f  = tid + k * 256;
            int r  = f >> 3;
            int c4 = f & 7;
            float4 v = *(const float4*)(x + (size_t)(rows0 + r) * EDIM + e0 + c4 * 4);
            float vv[4] = { v.x, v.y, v.z, v.w };
            #pragma unroll
            for (int i = 0; i < 4; i++) {
                __half h, l; split1(vv[i], h, l);
                Xh[r * 40 + c4 * 4 + i] = h;
                Xl[r * 40 + c4 * 4 + i] = l;
            }
        }
        #pragma unroll
        for (int k = 0; k < 6; k++) {
            int f  = tid + k * 256;
            int r  = f >> 3;
            int c4 = f & 7;
            const float* src = (r < 64)  ? wk + (size_t)r * EDIM
                             : (r < 128) ? wq + (size_t)(r - 64) * EDIM
                                         : wv + (size_t)(r - 128) * EDIM;
            float4 v = *(const float4*)(src + e0 + c4 * 4);
            float vv[4] = { v.x, v.y, v.z, v.w };
            #pragma unroll
            for (int i = 0; i < 4; i++) {
                __half h, l; split1(vv[i], h, l);
                Wh[r * 40 + c4 * 4 + i] = h;
                Wl[r * 40 + c4 * 4 + i] = l;
            }
        }
        __syncthreads();

        const unsigned* Xh32 = (const unsigned*)Xh;
        const unsigned* Xl32 = (const unsigned*)Xl;
        const unsigned* Wh32 = (const unsigned*)Wh;
        const unsigned* Wl32 = (const unsigned*)Wl;

        #pragma unroll
        for (int kc = 0; kc < 2; kc++) {
            int ab = (16 * rg + g) * 20 + 8 * kc + cq;
            unsigned ah[4] = { Xh32[ab], Xh32[ab + 160], Xh32[ab + 4], Xh32[ab + 164] };
            unsigned al[4] = { Xl32[ab], Xl32[ab + 160], Xl32[ab + 4], Xl32[ab + 164] };
            #pragma unroll
            for (int j = 0; j < 12; j++) {
                int n0 = cg * 96 + 8 * j;
                int bb = (n0 + g) * 20 + 8 * kc + cq;
                unsigned bh[2] = { Wh32[bb], Wh32[bb + 4] };
                unsigned bl[2] = { Wl32[bb], Wl32[bb + 4] };
                mma16816(acc[j], ah, bh);
                mma16816(acc[j], ah, bl);
                mma16816(acc[j], al, bh);
            }
        }
        __syncthreads();
    }

    const int row_lo = rows0 + 16 * rg + g;
    const int row_hi = row_lo + 8;
    #pragma unroll
    for (int j = 0; j < 12; j++) {
        int colg = cg * 96 + 8 * j + 2 * cq;
        __half *dh, *dl;
        float sc = 1.f;
        int cl;
        if (colg < 64)       { dh = g_Kh; dl = g_Kl; cl = colg; }
        else if (colg < 128) { dh = g_Qh; dl = g_Ql; cl = colg - 64; sc = 0.125f; }
        else                 { dh = g_Vh; dl = g_Vl; cl = colg - 128; }

        float v0 = acc[j][0] * sc, v1 = acc[j][1] * sc;
        float v2 = acc[j][2] * sc, v3 = acc[j][3] * sc;
        __half h0, l0, h1, l1; split1(v0, h0, l0); split1(v1, h1, l1);
        *(__half2*)(dh + (size_t)row_lo * ADIM + cl) = __halves2half2(h0, h1);
        *(__half2*)(dl + (size_t)row_lo * ADIM + cl) = __halves2half2(l0, l1);
        split1(v2, h0, l0); split1(v3, h1, l1);
        *(__half2*)(dh + (size_t)row_hi * ADIM + cl) = __halves2half2(h0, h1);
        *(__half2*)(dl + (size_t)row_hi * ADIM + cl) = __halves2half2(l0, l1);
    }
}

// ---------------------------------------------------------------------------
// Causal flash attention, split-KV. Block = (q-tile, split s, batch).
// Split s handles kb = s, s+NS, ... <= qi. Partials (O, m, l) -> global.
// ---------------------------------------------------------------------------
#define ST 72
#define SW 36
#define OFF_KH 0
#define OFF_KL 4608
#define OFF_VH 9216
#define OFF_VL 13824
#define OFF_PH 18432
#define OFF_PL 23040
#define SMEM_HALVES 27648

__global__ __launch_bounds__(128, 4)
void attn_kernel()
{
    extern __shared__ __align__(16) __half sh[];

    const int tid  = threadIdx.x;
    const int w    = tid >> 5;
    const int lane = tid & 31;
    const int g    = lane >> 2;
    const int cq   = lane & 3;
    const int bx   = blockIdx.x;
    const int s    = bx & (NS - 1);
    const int qi   = (SEQ / 64 - 1) - (bx >> 2);   // heavy q-tiles first
    const int b    = blockIdx.y;
    const int q0   = qi * 64;

    if (qi < s) return;  // this split has no KV tiles

    // Resident Q fragments (pre-scaled at projection)
    unsigned qh[4][4], ql[4][4];
    {
        size_t rl = (size_t)(b * SEQ + q0 + 16 * w + g) * ADIM;
        size_t rh = rl + 8 * ADIM;
        #pragma unroll
        for (int kc = 0; kc < 4; kc++) {
            int off = 16 * kc + 2 * cq;
            qh[kc][0] = *(const unsigned*)(g_Qh + rl + off);
            qh[kc][1] = *(const unsigned*)(g_Qh + rh + off);
            qh[kc][2] = *(const unsigned*)(g_Qh + rl + off + 8);
            qh[kc][3] = *(const unsigned*)(g_Qh + rh + off + 8);
            ql[kc][0] = *(const unsigned*)(g_Ql + rl + off);
            ql[kc][1] = *(const unsigned*)(g_Ql + rh + off);
            ql[kc][2] = *(const unsigned*)(g_Ql + rl + off + 8);
            ql[kc][3] = *(const unsigned*)(g_Ql + rh + off + 8);
        }
    }

    float o[8][4];
    #pragma unroll
    for (int j = 0; j < 8; j++)
        #pragma unroll
        for (int i = 0; i < 4; i++) o[j][i] = 0.f;
    float m_lo = -1e30f, m_hi = -1e30f, l_lo = 0.f, l_hi = 0.f;

    for (int kb = s; kb <= qi; kb += NS) {
        __syncthreads();
        {
            const __half* sKh = g_Kh + (size_t)(b * SEQ + kb * 64) * ADIM;
            const __half* sKl = g_Kl + (size_t)(b * SEQ + kb * 64) * ADIM;
            #pragma unroll
            for (int k = 0; k < 4; k++) {
                int f = tid + 128 * k;
                int r = f >> 3, c = f & 7;
                *(uint4*)(sh + OFF_KH + r * ST + 8 * c) = *(const uint4*)(sKh + r * ADIM + 8 * c);
                *(uint4*)(sh + OFF_KL + r * ST + 8 * c) = *(const uint4*)(sKl + r * ADIM + 8 * c);
            }
        }
        {
            int kp = tid & 31;
            int a0 = (tid >> 5) * 16;
            const __half* r0h = g_Vh + (size_t)(b * SEQ + kb * 64 + 2 * kp) * ADIM + a0;
            const __half* r0l = g_Vl + (size_t)(b * SEQ + kb * 64 + 2 * kp) * ADIM + a0;
            H8 xh0 = *(const H8*)(r0h),      xh1 = *(const H8*)(r0h + 8);
            H8 yh0 = *(const H8*)(r0h + 64), yh1 = *(const H8*)(r0h + 72);
            H8 xl0 = *(const H8*)(r0l),      xl1 = *(const H8*)(r0l + 8);
            H8 yl0 = *(const H8*)(r0l + 64), yl1 = *(const H8*)(r0l + 72);
            #pragma unroll
            for (int i = 0; i < 8; i++) {
                *(__half2*)(sh + OFF_VH + (a0 + i) * ST + 2 * kp)     = __halves2half2(xh0.h[i], yh0.h[i]);
                *(__half2*)(sh + OFF_VH + (a0 + 8 + i) * ST + 2 * kp) = __halves2half2(xh1.h[i], yh1.h[i]);
                *(__half2*)(sh + OFF_VL + (a0 + i) * ST + 2 * kp)     = __halves2half2(xl0.h[i], yl0.h[i]);
                *(__half2*)(sh + OFF_VL + (a0 + 8 + i) * ST + 2 * kp) = __halves2half2(xl1.h[i], yl1.h[i]);
            }
        }
        __syncthreads();

        // ---- S = Q K^T
        float sreg[8][4];
        #pragma unroll
        for (int j = 0; j < 8; j++)
            #pragma unroll
            for (int i = 0; i < 4; i++) sreg[j][i] = 0.f;

        const unsigned* Kh32 = (const unsigned*)(sh + OFF_KH);
        const unsigned* Kl32 = (const unsigned*)(sh + OFF_KL);
        #pragma unroll
        for (int kc = 0; kc < 4; kc++) {
            #pragma unroll
            for (int j = 0; j < 8; j++) {
                int bb = (8 * j + g) * SW + 8 * kc + cq;
                unsigned bh[2] = { Kh32[bb], Kh32[bb + 4] };
                unsigned bl[2] = { Kl32[bb], Kl32[bb + 4] };
                mma16816(sreg[j], qh[kc], bh);
                mma16816(sreg[j], qh[kc], bl);
                mma16816(sreg[j], ql[kc], bh);
            }
        }

        if (kb == qi) {
            int r_lo = 16 * w + g, r_hi = r_lo + 8;
            #pragma unroll
            for (int j = 0; j < 8; j++) {
                int c0 = 8 * j + 2 * cq;
                if (c0     > r_lo) sreg[j][0] = -1e30f;
                if (c0 + 1 > r_lo) sreg[j][1] = -1e30f;
                if (c0     > r_hi) sreg[j][2] = -1e30f;
                if (c0 + 1 > r_hi) sreg[j][3] = -1e30f;
            }
        }

        // ---- online softmax
        float mx0 = -1e30f, mx1 = -1e30f;
        #pragma unroll
        for (int j = 0; j < 8; j++) {
            mx0 = fmaxf(mx0, fmaxf(sreg[j][0], sreg[j][1]));
            mx1 = fmaxf(mx1, fmaxf(sreg[j][2], sreg[j][3]));
        }
        mx0 = fmaxf(mx0, __shfl_xor_sync(0xffffffffu, mx0, 1));
        mx0 = fmaxf(mx0, __shfl_xor_sync(0xffffffffu, mx0, 2));
        mx1 = fmaxf(mx1, __shfl_xor_sync(0xffffffffu, mx1, 1));
        mx1 = fmaxf(mx1, __shfl_xor_sync(0xffffffffu, mx1, 2));
        float mn0 = fmaxf(m_lo, mx0), mn1 = fmaxf(m_hi, mx1);
        float sc0 = __expf(m_lo - mn0), sc1 = __expf(m_hi - mn1);
        m_lo = mn0; m_hi = mn1;
        float su0 = 0.f, su1 = 0.f;
        #pragma unroll
        for (int j = 0; j < 8; j++) {
            sreg[j][0] = __expf(sreg[j][0] - mn0);
            sreg[j][1] = __expf(sreg[j][1] - mn0);
            sreg[j][2] = __expf(sreg[j][2] - mn1);
            sreg[j][3] = __expf(sreg[j][3] - mn1);
            su0 += sreg[j][0] + sreg[j][1];
            su1 += sreg[j][2] + sreg[j][3];
        }
        su0 += __shfl_xor_sync(0xffffffffu, su0, 1);
        su0 += __shfl_xor_sync(0xffffffffu, su0, 2);
        su1 += __shfl_xor_sync(0xffffffffu, su1, 1);
        su1 += __shfl_xor_sync(0xffffffffu, su1, 2);
        l_lo = l_lo * sc0 + su0;
        l_hi = l_hi * sc1 + su1;
        #pragma unroll
        for (int j = 0; j < 8; j++) {
            o[j][0] *= sc0; o[j][1] *= sc0;
            o[j][2] *= sc1; o[j][3] *= sc1;
        }

        // ---- write P (split) into per-warp region
        #pragma unroll
        for (int j = 0; j < 8; j++) {
            int hc = 8 * j + 2 * cq;
            __half h0, l0, h1, l1;
            split1(sreg[j][0], h0, l0); split1(sreg[j][1], h1, l1);
            *(__half2*)(sh + OFF_PH + (16 * w + g) * ST + hc) = __halves2half2(h0, h1);
            *(__half2*)(sh + OFF_PL + (16 * w + g) * ST + hc) = __halves2half2(l0, l1);
            split1(sreg[j][2], h0, l0); split1(sreg[j][3], h1, l1);
            *(__half2*)(sh + OFF_PH + (16 * w + g + 8) * ST + hc) = __halves2half2(h0, h1);
            *(__half2*)(sh + OFF_PL + (16 * w + g + 8) * ST + hc) = __halves2half2(l0, l1);
        }
        __syncwarp();

        // ---- O += P V
        const unsigned* Ph32 = (const unsigned*)(sh + OFF_PH);
        const unsigned* Pl32 = (const unsigned*)(sh + OFF_PL);
        const unsigned* Vh32 = (const unsigned*)(sh + OFF_VH);
        const unsigned* Vl32 = (const unsigned*)(sh + OFF_VL);
        #pragma unroll
        for (int kc = 0; kc < 4; kc++) {
            int ab = (16 * w + g) * SW + 8 * kc + cq;
            unsigned ah[4] = { Ph32[ab], Ph32[ab + 8 * SW], Ph32[ab + 4], Ph32[ab + 8 * SW + 4] };
            unsigned al[4] = { Pl32[ab], Pl32[ab + 8 * SW], Pl32[ab + 4], Pl32[ab + 8 * SW + 4] };
            #pragma unroll
            for (int j = 0; j < 8; j++) {
                int bb = (8 * j + g) * SW + 8 * kc + cq;
                unsigned bh[2] = { Vh32[bb], Vh32[bb + 4] };
                unsigned bl[2] = { Vl32[bb], Vl32[bb + 4] };
                mma16816(o[j], ah, bh);
                mma16816(o[j], ah, bl);
                mma16816(o[j], al, bh);
            }
        }
    }

    // ---- epilogue: write unnormalized partial O + (m, l)
    const int row_lo = q0 + 16 * w + g;
    const int row_hi = row_lo + 8;
    const size_t sb  = (size_t)(b * NS + s) * SEQ;
    #pragma unroll
    for (int j = 0; j < 8; j++) {
        int col = 8 * j + 2 * cq;
        *(float2*)(g_Om + (sb + row_lo) * ADIM + col) = make_float2(o[j][0], o[j][1]);
        *(float2*)(g_Om + (sb + row_hi) * ADIM + col) = make_float2(o[j][2], o[j][3]);
    }
    if (cq == 0) {
        g_m[sb + row_lo] = m_lo;  g_l[sb + row_lo] = l_lo;
        g_m[sb + row_hi] = m_hi;  g_l[sb + row_hi] = l_hi;
    }
}

// ---------------------------------------------------------------------------
// Combine split-KV partials: out = (sum_s e^{m_s-m} O_s) / (sum_s e^{m_s-m} l_s)
// Block 128: 8 rows x 16 threads; each thread 4 consecutive cols.
// ---------------------------------------------------------------------------
__global__ __launch_bounds__(128)
void combine_kernel(float* __restrict__ out)
{
    const int tid = threadIdx.x;
    const int row = blockIdx.x * 8 + (tid >> 4);
    const int b   = blockIdx.y;
    const int c0  = (tid & 15) * 4;
    const int qi  = row >> 6;
    const int ns  = (qi + 1 < NS) ? (qi + 1) : NS;

    float m = -1e30f;
    #pragma unroll
    for (int s = 0; s < NS; s++)
        if (s < ns) m = fmaxf(m, g_m[(size_t)(b * NS + s) * SEQ + row]);

    float l = 0.f;
    float4 acc = make_float4(0.f, 0.f, 0.f, 0.f);
    #pragma unroll
    for (int s = 0; s < NS; s++) {
        if (s >= ns) break;
        size_t sb = (size_t)(b * NS + s) * SEQ + row;
        float wgt = __expf(g_m[sb] - m);
        l += g_l[sb] * wgt;
        float4 v = *(const float4*)(g_Om + sb * ADIM + c0);
        acc.x += v.x * wgt; acc.y += v.y * wgt;
        acc.z += v.z * wgt; acc.w += v.w * wgt;
    }
    float inv = 1.f / l;
    float4 r;
    r.x = rintf(acc.x * inv * 1e4f) * 1e-4f;
    r.y = rintf(acc.y * inv * 1e4f) * 1e-4f;
    r.z = rintf(acc.z * inv * 1e4f) * 1e-4f;
    r.w = rintf(acc.w * inv * 1e4f) * 1e-4f;
    *(float4*)(out + ((size_t)b * SEQ + row) * ADIM + c0) = r;
}

extern "C" void kernel_launch(void* const* d_in, const int* in_sizes, int n_in,
                              void* d_out, int out_size)
{
    const float* x  = (const float*)d_in[0];
    const float* wk = (const float*)d_in[1];
    const float* wq = (const float*)d_in[2];
    const float* wv = (const float*)d_in[3];
    float* out = (float*)d_out;

    qkv_proj<<<(NB * SEQ) / 64, 256>>>(x, wk, wq, wv);

    int smem = SMEM_HALVES * (int)sizeof(__half);  // 55296 B
    cudaFuncSetAttribute(attn_kernel, cudaFuncAttributeMaxDynamicSharedMemorySize, smem);
    attn_kernel<<<dim3((SEQ / 64) * NS, NB), 128, smem>>>();

    combine_kernel<<<dim3(SEQ / 8, NB), 128>>>(out);
}